// round 1
// baseline (speedup 1.0000x reference)
#include <cuda_runtime.h>

#define BB 4
#define TT 256
#define DD 256
#define HH 4
#define DKK 64
#define NREL 64
#define NT (BB*TT)   // 1024

// Scratch (device globals: no allocation allowed)
__device__ float g_q[NT*DD];
__device__ float g_k[NT*DD];
__device__ float g_v[NT*DD];
__device__ float g_agg[NT*DD];

// ---------------------------------------------------------------------------
// K1: fused QKV projection.  out[n,e] = sum_d x[n,d] * W[e,d] + bias[e]
// Block tile 64n x 64e, K-chunks of 64. blockIdx.z selects q/k/v.
// ---------------------------------------------------------------------------
__global__ void qkv_kernel(const float* __restrict__ x,
                           const float* __restrict__ Wq, const float* __restrict__ Wk,
                           const float* __restrict__ Wv,
                           const float* __restrict__ bq, const float* __restrict__ bk,
                           const float* __restrict__ bv) {
    __shared__ float As[64*65];
    __shared__ float Bs[64*65];
    int n0 = blockIdx.x * 64;
    int e0 = blockIdx.y * 64;
    const float* W; const float* bias; float* out;
    if (blockIdx.z == 0)      { W = Wq; bias = bq; out = g_q; }
    else if (blockIdx.z == 1) { W = Wk; bias = bk; out = g_k; }
    else                      { W = Wv; bias = bv; out = g_v; }
    int t  = threadIdx.x;
    int el = t & 15, nl = t >> 4;
    float acc[4][4];
    #pragma unroll
    for (int i = 0; i < 4; i++)
        #pragma unroll
        for (int j = 0; j < 4; j++) acc[i][j] = 0.f;

    for (int d0 = 0; d0 < DD; d0 += 64) {
        __syncthreads();
        #pragma unroll
        for (int r = 0; r < 16; r++) {
            int idx = t + 256*r;
            int row = idx >> 6, col = idx & 63;
            As[row*65+col] = x[(n0+row)*DD + d0 + col];
            Bs[row*65+col] = W[(e0+row)*DD + d0 + col];
        }
        __syncthreads();
        #pragma unroll 16
        for (int dd = 0; dd < 64; dd++) {
            float a[4], b[4];
            #pragma unroll
            for (int i = 0; i < 4; i++) a[i] = As[(nl+16*i)*65 + dd];
            #pragma unroll
            for (int j = 0; j < 4; j++) b[j] = Bs[(el+16*j)*65 + dd];
            #pragma unroll
            for (int i = 0; i < 4; i++)
                #pragma unroll
                for (int j = 0; j < 4; j++)
                    acc[i][j] += a[i]*b[j];
        }
    }
    #pragma unroll
    for (int i = 0; i < 4; i++) {
        int n = n0 + nl + 16*i;
        #pragma unroll
        for (int j = 0; j < 4; j++) {
            int e = e0 + el + 16*j;
            out[n*DD + e] = acc[i][j] + bias[e];
        }
    }
}

// ---------------------------------------------------------------------------
// K2: fused attention. One block per (b, h, 16-row i-tile).
//   qr[ii][rel] = <q_ii, rel_k[rel]_h>
//   s[ii][j]    = (<q_ii, k_j> + qr[ii][spatial]) / 8 -> softmax over j
//   w[ii][rel]  = sum_j attn * [spatial==rel]   (shared atomics)
//   agg[ii][d]  = attn @ V_h + w @ rel_v_h
// ---------------------------------------------------------------------------
__global__ void attn_kernel(const int*  __restrict__ spatial,
                            const float* __restrict__ rel_k,
                            const float* __restrict__ rel_v) {
    __shared__ float Qs [16*65];
    __shared__ float QRs[16*65];
    __shared__ float Ss [16*257];
    __shared__ float Ws [16*65];
    __shared__ float KVs[64*65];

    int it = blockIdx.x, h = blockIdx.y, b = blockIdx.z;
    int i0 = it * 16;
    int t  = threadIdx.x;
    int hd = h * DKK;

    // P0: load Q tile [16 x 64]
    #pragma unroll
    for (int r = 0; r < 4; r++) {
        int idx = t + 256*r;
        int ii = idx >> 6, d = idx & 63;
        Qs[ii*65+d] = g_q[(b*TT + i0 + ii)*DD + hd + d];
    }
    // P1: load rel_k head-slice [64 x 64]
    #pragma unroll
    for (int r = 0; r < 16; r++) {
        int idx = t + 256*r;
        int rel = idx >> 6, d = idx & 63;
        KVs[rel*65+d] = rel_k[rel*DD + hd + d];
    }
    // zero W accumulators
    for (int idx = t; idx < 16*65; idx += 256) Ws[idx] = 0.f;
    __syncthreads();

    // P2: qr[ii][rel]
    #pragma unroll
    for (int r = 0; r < 4; r++) {
        int o = t + 256*r;
        int ii = o >> 6, rel = o & 63;
        float s = 0.f;
        #pragma unroll 16
        for (int d = 0; d < 64; d++) s += Qs[ii*65+d]*KVs[rel*65+d];
        QRs[ii*65+rel] = s;
    }

    // P3: scores (2x2 register tile per thread: ii in {iil,iil+1}, jj in {jjl, jjl+32})
    int jjl = t & 31;
    int iil = (t >> 5) * 2;
    for (int jt = 0; jt < 4; jt++) {
        __syncthreads();
        #pragma unroll
        for (int r = 0; r < 16; r++) {
            int idx = t + 256*r;
            int jj = idx >> 6, d = idx & 63;
            KVs[jj*65+d] = g_k[(b*TT + jt*64 + jj)*DD + hd + d];
        }
        __syncthreads();
        float s00=0.f, s01=0.f, s10=0.f, s11=0.f;
        #pragma unroll 16
        for (int d = 0; d < 64; d++) {
            float q0 = Qs[iil*65+d],      q1 = Qs[(iil+1)*65+d];
            float k0 = KVs[jjl*65+d],     k1 = KVs[(jjl+32)*65+d];
            s00 += q0*k0; s01 += q0*k1; s10 += q1*k0; s11 += q1*k1;
        }
        int base0 = (b*TT + i0 + iil)*TT + jt*64;
        int base1 = base0 + TT;
        int r00 = spatial[base0 + jjl];
        int r01 = spatial[base0 + jjl + 32];
        int r10 = spatial[base1 + jjl];
        int r11 = spatial[base1 + jjl + 32];
        Ss[iil*257     + jt*64 + jjl]      = (s00 + QRs[iil*65+r00])     * 0.125f;
        Ss[iil*257     + jt*64 + jjl+32]   = (s01 + QRs[iil*65+r01])     * 0.125f;
        Ss[(iil+1)*257 + jt*64 + jjl]      = (s10 + QRs[(iil+1)*65+r10]) * 0.125f;
        Ss[(iil+1)*257 + jt*64 + jjl+32]   = (s11 + QRs[(iil+1)*65+r11]) * 0.125f;
    }
    __syncthreads();

    // P4: softmax over j, per row (8 warps x 2 rows)
    int w = t >> 5, lane = t & 31;
    #pragma unroll
    for (int rr = 0; rr < 2; rr++) {
        int ii = w*2 + rr;
        float vals[8];
        float vmax = -1e30f;
        #pragma unroll
        for (int k = 0; k < 8; k++) {
            vals[k] = Ss[ii*257 + lane + 32*k];
            vmax = fmaxf(vmax, vals[k]);
        }
        #pragma unroll
        for (int o = 16; o > 0; o >>= 1)
            vmax = fmaxf(vmax, __shfl_xor_sync(0xffffffff, vmax, o));
        float sum = 0.f;
        #pragma unroll
        for (int k = 0; k < 8; k++) { vals[k] = __expf(vals[k] - vmax); sum += vals[k]; }
        #pragma unroll
        for (int o = 16; o > 0; o >>= 1)
            sum += __shfl_xor_sync(0xffffffff, sum, o);
        float inv = 1.f / sum;
        #pragma unroll
        for (int k = 0; k < 8; k++)
            Ss[ii*257 + lane + 32*k] = vals[k] * inv;
    }
    __syncthreads();

    // P5: relation histogram w[ii][rel] += attn  (shared atomics; thread t owns column j=t)
    for (int ii = 0; ii < 16; ii++) {
        int rel = spatial[(b*TT + i0 + ii)*TT + t];
        atomicAdd(&Ws[ii*65 + rel], Ss[ii*257 + t]);
    }
    __syncthreads();

    // P6: agg = attn @ V_h  +  w @ rel_v_h
    int dl = t & 31;
    float a00=0.f, a01=0.f, a10=0.f, a11=0.f;
    for (int jt = 0; jt < 4; jt++) {
        __syncthreads();
        #pragma unroll
        for (int r = 0; r < 16; r++) {
            int idx = t + 256*r;
            int jj = idx >> 6, d = idx & 63;
            KVs[jj*65+d] = g_v[(b*TT + jt*64 + jj)*DD + hd + d];
        }
        __syncthreads();
        #pragma unroll 16
        for (int jj = 0; jj < 64; jj++) {
            float p0 = Ss[iil*257     + jt*64 + jj];
            float p1 = Ss[(iil+1)*257 + jt*64 + jj];
            float v0 = KVs[jj*65 + dl];
            float v1 = KVs[jj*65 + dl + 32];
            a00 += p0*v0; a01 += p0*v1; a10 += p1*v0; a11 += p1*v1;
        }
    }
    __syncthreads();
    #pragma unroll
    for (int r = 0; r < 16; r++) {
        int idx = t + 256*r;
        int rel = idx >> 6, d = idx & 63;
        KVs[rel*65+d] = rel_v[rel*DD + hd + d];
    }
    __syncthreads();
    #pragma unroll 16
    for (int rel = 0; rel < 64; rel++) {
        float w0 = Ws[iil*65 + rel];
        float w1 = Ws[(iil+1)*65 + rel];
        float v0 = KVs[rel*65 + dl];
        float v1 = KVs[rel*65 + dl + 32];
        a00 += w0*v0; a01 += w0*v1; a10 += w1*v0; a11 += w1*v1;
    }
    int row0 = (b*TT + i0 + iil)*DD + hd;
    int row1 = row0 + DD;
    g_agg[row0 + dl]      = a00;
    g_agg[row0 + dl + 32] = a01;
    g_agg[row1 + dl]      = a10;
    g_agg[row1 + dl + 32] = a11;
}

// ---------------------------------------------------------------------------
// K3: out = agg @ Wo^T + bo + x  -> LayerNorm(gamma,beta) -> ReLU
// Block handles 16 full rows (needed for LayerNorm). 64 blocks.
// ---------------------------------------------------------------------------
__global__ void out_kernel(const float* __restrict__ x,  const float* __restrict__ Wo,
                           const float* __restrict__ bo, const float* __restrict__ gamma,
                           const float* __restrict__ beta, float* __restrict__ out) {
    __shared__ float Ag[16*256];
    __shared__ float WoS[64*65];   // reused as OutS[16*256] after GEMM
    int n0 = blockIdx.x * 16;
    int t  = threadIdx.x;
    #pragma unroll
    for (int r = 0; r < 16; r++) {
        int idx = t + 256*r;
        Ag[idx] = g_agg[n0*DD + idx];
    }
    int el  = t & 31;
    int iil = (t >> 5) * 2;
    float acc[4][4];
    for (int et = 0; et < 4; et++) {
        acc[et][0] = acc[et][1] = acc[et][2] = acc[et][3] = 0.f;
        for (int dt = 0; dt < 4; dt++) {
            __syncthreads();
            #pragma unroll
            for (int r = 0; r < 16; r++) {
                int idx = t + 256*r;
                int ee = idx >> 6, dd = idx & 63;
                WoS[ee*65+dd] = Wo[(et*64+ee)*DD + dt*64 + dd];
            }
            __syncthreads();
            #pragma unroll 16
            for (int dd = 0; dd < 64; dd++) {
                float a0 = Ag[iil*256     + dt*64 + dd];
                float a1 = Ag[(iil+1)*256 + dt*64 + dd];
                float w0 = WoS[el*65 + dd];
                float w1 = WoS[(el+32)*65 + dd];
                acc[et][0] += a0*w0; acc[et][1] += a0*w1;
                acc[et][2] += a1*w0; acc[et][3] += a1*w1;
            }
        }
    }
    __syncthreads();
    float* OutS = WoS;  // 16*256 <= 64*65
    #pragma unroll
    for (int et = 0; et < 4; et++) {
        int e0 = et*64 + el;
        float b0v = bo[e0], b1v = bo[e0+32];
        OutS[iil*256     + e0]    = acc[et][0] + b0v + x[(n0+iil)*DD + e0];
        OutS[iil*256     + e0+32] = acc[et][1] + b1v + x[(n0+iil)*DD + e0+32];
        OutS[(iil+1)*256 + e0]    = acc[et][2] + b0v + x[(n0+iil+1)*DD + e0];
        OutS[(iil+1)*256 + e0+32] = acc[et][3] + b1v + x[(n0+iil+1)*DD + e0+32];
    }
    __syncthreads();
    int w = t >> 5, lane = t & 31;
    #pragma unroll
    for (int rr = 0; rr < 2; rr++) {
        int ii = w*2 + rr;
        float vals[8];
        float sum = 0.f, sq = 0.f;
        #pragma unroll
        for (int k = 0; k < 8; k++) {
            vals[k] = OutS[ii*256 + lane + 32*k];
            sum += vals[k]; sq += vals[k]*vals[k];
        }
        #pragma unroll
        for (int o = 16; o > 0; o >>= 1) {
            sum += __shfl_xor_sync(0xffffffff, sum, o);
            sq  += __shfl_xor_sync(0xffffffff, sq,  o);
        }
        float mu  = sum * (1.f/256.f);
        float var = sq  * (1.f/256.f) - mu*mu;
        float inv = rsqrtf(var + 1e-5f);
        #pragma unroll
        for (int k = 0; k < 8; k++) {
            int e = lane + 32*k;
            float y = (vals[k] - mu) * inv * gamma[e] + beta[e];
            out[(n0+ii)*DD + e] = fmaxf(y, 0.f);
        }
    }
}

extern "C" void kernel_launch(void* const* d_in, const int* in_sizes, int n_in,
                              void* d_out, int out_size) {
    const float* x       = (const float*)d_in[0];
    const int*   spatial = (const int*)  d_in[1];
    const float* Wq      = (const float*)d_in[2];
    const float* bq      = (const float*)d_in[3];
    const float* Wk      = (const float*)d_in[4];
    const float* bk      = (const float*)d_in[5];
    const float* Wv      = (const float*)d_in[6];
    const float* bv      = (const float*)d_in[7];
    const float* rel_k   = (const float*)d_in[8];
    const float* rel_v   = (const float*)d_in[9];
    const float* Wo      = (const float*)d_in[10];
    const float* bo      = (const float*)d_in[11];
    const float* gamma   = (const float*)d_in[12];
    const float* beta    = (const float*)d_in[13];
    float* out = (float*)d_out;

    qkv_kernel <<<dim3(16, 4, 3), 256>>>(x, Wq, Wk, Wv, bq, bk, bv);
    attn_kernel<<<dim3(16, 4, 4), 256>>>(spatial, rel_k, rel_v);
    out_kernel <<<64, 256>>>(x, Wo, bo, gamma, beta, out);
}

// round 6
// speedup vs baseline: 1.4069x; 1.4069x over previous
#include <cuda_runtime.h>

#define BB 4
#define TT 256
#define DD 256
#define HH 4
#define DKK 64
#define NREL 64
#define NT (BB*TT)   // 1024

__device__ float g_q[NT*DD];
__device__ float g_k[NT*DD];
__device__ float g_v[NT*DD];
__device__ float g_agg[NT*DD];

// ---------------------------------------------------------------------------
// K1: fused QKV projection. out[n,e] = sum_d x[n,d]*W[e,d] + b[e]
// 128 threads, tile 64n x 64e, K-chunks 64, swizzled smem, float4 everywhere.
// Per-thread fragment: 4n x 8e.
// ---------------------------------------------------------------------------
__global__ void __launch_bounds__(128) qkv_kernel(
        const float* __restrict__ x,
        const float* __restrict__ Wq, const float* __restrict__ Wk,
        const float* __restrict__ Wv,
        const float* __restrict__ bq, const float* __restrict__ bk,
        const float* __restrict__ bv) {
    __shared__ float As[64*64];
    __shared__ float Bs[64*64];
    int n0 = blockIdx.x * 64;
    int e0 = blockIdx.y * 64;
    const float* W; const float* bias; float* out;
    if (blockIdx.z == 0)      { W = Wq; bias = bq; out = g_q; }
    else if (blockIdx.z == 1) { W = Wk; bias = bk; out = g_k; }
    else                      { W = Wv; bias = bv; out = g_v; }

    int t  = threadIdx.x;
    int el = t & 7;          // e = el + 8j, j=0..7
    int nl = t >> 3;         // n = nl + 16i, i=0..3   (nl 0..15)
    float acc[4][8];
    #pragma unroll
    for (int i = 0; i < 4; i++)
        #pragma unroll
        for (int j = 0; j < 8; j++) acc[i][j] = 0.f;

    int lrow = t >> 4;       // 0..7
    int lq   = t & 15;       // quad 0..15

    for (int d0 = 0; d0 < DD; d0 += 64) {
        __syncthreads();
        #pragma unroll
        for (int r = 0; r < 8; r++) {
            int row = lrow + 8*r;
            float4 va = *(const float4*)&x[(n0+row)*DD + d0 + lq*4];
            float4 vb = *(const float4*)&W[(e0+row)*DD + d0 + lq*4];
            *(float4*)&As[row*64 + ((lq ^ (row&15))<<2)] = va;
            *(float4*)&Bs[row*64 + ((lq ^ (row&15))<<2)] = vb;
        }
        __syncthreads();
        #pragma unroll 16
        for (int q16 = 0; q16 < 16; q16++) {
            float4 a[4], b[8];
            #pragma unroll
            for (int i = 0; i < 4; i++) {
                int row = nl + 16*i;
                a[i] = *(const float4*)&As[row*64 + ((q16 ^ (row&15))<<2)];
            }
            #pragma unroll
            for (int j = 0; j < 8; j++) {
                int row = el + 8*j;
                b[j] = *(const float4*)&Bs[row*64 + ((q16 ^ (row&15))<<2)];
            }
            #pragma unroll
            for (int i = 0; i < 4; i++)
                #pragma unroll
                for (int j = 0; j < 8; j++) {
                    acc[i][j] += a[i].x*b[j].x + a[i].y*b[j].y
                               + a[i].z*b[j].z + a[i].w*b[j].w;
                }
        }
    }
    #pragma unroll
    for (int i = 0; i < 4; i++) {
        int n = n0 + nl + 16*i;
        #pragma unroll
        for (int j = 0; j < 8; j++) {
            int e = e0 + el + 8*j;
            out[n*DD + e] = acc[i][j] + bias[e];
        }
    }
}

// ---------------------------------------------------------------------------
// K2: fused attention. One block per (b, h, 16-row i-tile). 256 threads.
// Dynamic smem: full K/V tile resident (256x68).
// ---------------------------------------------------------------------------
#define ATTN_SMEM_FLOATS (256*68 + 16*68 + 16*68 + 16*260 + 16*68)
// layout: KVs[256*68] | Qs[16*68] | QRs[16*68] | Ss[16*260] | Ws[16*68]

extern __shared__ float sm[];

__global__ void __launch_bounds__(256) attn_kernel(
        const int*  __restrict__ spatial,
        const float* __restrict__ rel_k,
        const float* __restrict__ rel_v) {
    float* KVs = sm;
    float* Qs  = KVs + 256*68;
    float* QRs = Qs  + 16*68;
    float* Ss  = QRs + 16*68;
    float* Ws  = Ss  + 16*260;

    int it = blockIdx.x, h = blockIdx.y, b = blockIdx.z;
    int i0 = it * 16;
    int t  = threadIdx.x;
    int hd = h * DKK;
    int w = t >> 5, lane = t & 31;

    // P0: Q tile [16x64] (1 float4/thread) + rel_k [64x64] (4 f4/thread) + zero Ws
    {
        int ii = t >> 4, q = t & 15;
        *(float4*)&Qs[ii*68 + q*4] =
            *(const float4*)&g_q[(b*TT + i0 + ii)*DD + hd + q*4];
        #pragma unroll
        for (int r = 0; r < 4; r++) {
            int row = (t>>4) + 16*r;
            *(float4*)&KVs[row*68 + q*4] =
                *(const float4*)&rel_k[row*DD + hd + q*4];
        }
    }
    for (int idx = t; idx < 16*68; idx += 256) Ws[idx] = 0.f;
    __syncthreads();

    // P2: qr[ii][rel] = <Q_ii, rel_k[rel]>
    #pragma unroll
    for (int rr = 0; rr < 4; rr++) {
        int o = t + 256*rr;
        int ii = o >> 6, rel = o & 63;
        float s = 0.f;
        #pragma unroll
        for (int q16 = 0; q16 < 16; q16++) {
            float4 qv = *(const float4*)&Qs[ii*68 + q16*4];
            float4 kv = *(const float4*)&KVs[rel*68 + q16*4];
            s += qv.x*kv.x + qv.y*kv.y + qv.z*kv.z + qv.w*kv.w;
        }
        QRs[ii*68 + rel] = s;
    }
    __syncthreads();

    // load full K [256x64] (16 f4/thread)
    {
        int q = t & 15;
        #pragma unroll
        for (int r = 0; r < 16; r++) {
            int row = (t>>4) + 16*r;
            *(float4*)&KVs[row*68 + q*4] =
                *(const float4*)&g_k[(b*TT + row)*DD + hd + q*4];
        }
    }
    __syncthreads();

    // P3: scores. warp w owns j in [32w, 32w+32). thread: i = il+4r, j = 32w+jl+8c.
    {
        int jl = lane & 7, il = lane >> 3;
        float s[4][4];
        #pragma unroll
        for (int r = 0; r < 4; r++)
            #pragma unroll
            for (int c = 0; c < 4; c++) s[r][c] = 0.f;
        #pragma unroll 8
        for (int q16 = 0; q16 < 16; q16++) {
            float4 qv[4], kv[4];
            #pragma unroll
            for (int r = 0; r < 4; r++)
                qv[r] = *(const float4*)&Qs[(il+4*r)*68 + q16*4];
            #pragma unroll
            for (int c = 0; c < 4; c++)
                kv[c] = *(const float4*)&KVs[(32*w + jl + 8*c)*68 + q16*4];
            #pragma unroll
            for (int r = 0; r < 4; r++)
                #pragma unroll
                for (int c = 0; c < 4; c++)
                    s[r][c] += qv[r].x*kv[c].x + qv[r].y*kv[c].y
                             + qv[r].z*kv[c].z + qv[r].w*kv[c].w;
        }
        #pragma unroll
        for (int r = 0; r < 4; r++) {
            int i = il + 4*r;
            #pragma unroll
            for (int c = 0; c < 4; c++) {
                int j = 32*w + jl + 8*c;
                int rel = spatial[(b*TT + i0 + i)*TT + j];
                Ss[i*260 + j] = (s[r][c] + QRs[i*68 + rel]) * 0.125f;
            }
        }
    }
    __syncthreads();

    // load V over K (safe: all warps past P3 due to the sync above)
    {
        int q = t & 15;
        #pragma unroll
        for (int r = 0; r < 16; r++) {
            int row = (t>>4) + 16*r;
            *(float4*)&KVs[row*68 + q*4] =
                *(const float4*)&g_v[(b*TT + row)*DD + hd + q*4];
        }
    }

    // P4: softmax, warp w handles rows 2w, 2w+1
    #pragma unroll
    for (int rr = 0; rr < 2; rr++) {
        int ii = w*2 + rr;
        float vals[8];
        float vmax = -1e30f;
        #pragma unroll
        for (int k = 0; k < 8; k++) {
            vals[k] = Ss[ii*260 + lane + 32*k];
            vmax = fmaxf(vmax, vals[k]);
        }
        #pragma unroll
        for (int o = 16; o > 0; o >>= 1)
            vmax = fmaxf(vmax, __shfl_xor_sync(0xffffffff, vmax, o));
        float sum = 0.f;
        #pragma unroll
        for (int k = 0; k < 8; k++) { vals[k] = __expf(vals[k] - vmax); sum += vals[k]; }
        #pragma unroll
        for (int o = 16; o > 0; o >>= 1)
            sum += __shfl_xor_sync(0xffffffff, sum, o);
        float inv = 1.f / sum;
        #pragma unroll
        for (int k = 0; k < 8; k++)
            Ss[ii*260 + lane + 32*k] = vals[k] * inv;
    }
    __syncthreads();   // covers V load + softmax completion

    // P5: relation histogram (thread t owns column j=t)
    #pragma unroll 4
    for (int ii = 0; ii < 16; ii++) {
        int rel = spatial[(b*TT + i0 + ii)*TT + t];
        atomicAdd(&Ws[ii*68 + rel], Ss[ii*260 + t]);
    }

    // P6a: agg partial = attn @ V. warp: iy=w&3 (i-base 4*iy), jh=w>>2 (j half).
    int iy = w & 3, jh = w >> 2;
    int il2 = lane >> 4, dq = lane & 15;
    int ib = 4*iy + 2*il2;
    float a6[2][4];
    #pragma unroll
    for (int r = 0; r < 2; r++)
        #pragma unroll
        for (int c = 0; c < 4; c++) a6[r][c] = 0.f;
    {
        int jbeg = 128*jh, jend = jbeg + 128;
        #pragma unroll 4
        for (int jj = jbeg; jj < jend; jj += 2) {
            float2 p0 = *(const float2*)&Ss[ib*260 + jj];
            float2 p1 = *(const float2*)&Ss[(ib+1)*260 + jj];
            float4 v0 = *(const float4*)&KVs[jj*68 + 4*dq];
            float4 v1 = *(const float4*)&KVs[(jj+1)*68 + 4*dq];
            a6[0][0] += p0.x*v0.x + p0.y*v1.x;
            a6[0][1] += p0.x*v0.y + p0.y*v1.y;
            a6[0][2] += p0.x*v0.z + p0.y*v1.z;
            a6[0][3] += p0.x*v0.w + p0.y*v1.w;
            a6[1][0] += p1.x*v0.x + p1.y*v1.x;
            a6[1][1] += p1.x*v0.y + p1.y*v1.y;
            a6[1][2] += p1.x*v0.z + p1.y*v1.z;
            a6[1][3] += p1.x*v0.w + p1.y*v1.w;
        }
    }
    __syncthreads();   // Ws complete (P5), KVs free

    // load rel_v into KVs[0:64]
    {
        int q = t & 15;
        #pragma unroll
        for (int r = 0; r < 4; r++) {
            int row = (t>>4) + 16*r;
            *(float4*)&KVs[row*68 + q*4] =
                *(const float4*)&rel_v[row*DD + hd + q*4];
        }
    }
    __syncthreads();

    // P6b: += w @ rel_v (jh splits rel range 64 into halves of 32)
    {
        int rbeg = 32*jh, rend = rbeg + 32;
        #pragma unroll 4
        for (int rr = rbeg; rr < rend; rr += 2) {
            float2 p0 = *(const float2*)&Ws[ib*68 + rr];
            float2 p1 = *(const float2*)&Ws[(ib+1)*68 + rr];
            float4 v0 = *(const float4*)&KVs[rr*68 + 4*dq];
            float4 v1 = *(const float4*)&KVs[(rr+1)*68 + 4*dq];
            a6[0][0] += p0.x*v0.x + p0.y*v1.x;
            a6[0][1] += p0.x*v0.y + p0.y*v1.y;
            a6[0][2] += p0.x*v0.z + p0.y*v1.z;
            a6[0][3] += p0.x*v0.w + p0.y*v1.w;
            a6[1][0] += p1.x*v0.x + p1.y*v1.x;
            a6[1][1] += p1.x*v0.y + p1.y*v1.y;
            a6[1][2] += p1.x*v0.z + p1.y*v1.z;
            a6[1][3] += p1.x*v0.w + p1.y*v1.w;
        }
    }

    // reduce two j-halves via shared (reuse Qs as 16x64 buffer)
    float* Rs = Qs;
    if (jh == 0) {
        #pragma unroll
        for (int r = 0; r < 2; r++)
            *(float4*)&Rs[(ib+r)*64 + 4*dq] = *(float4*)&a6[r][0];
    }
    __syncthreads();
    if (jh == 1) {
        #pragma unroll
        for (int r = 0; r < 2; r++) {
            float4 o = *(const float4*)&Rs[(ib+r)*64 + 4*dq];
            o.x += a6[r][0]; o.y += a6[r][1]; o.z += a6[r][2]; o.w += a6[r][3];
            *(float4*)&g_agg[(b*TT + i0 + ib + r)*DD + hd + 4*dq] = o;
        }
    }
}

// ---------------------------------------------------------------------------
// K3: out = agg @ Wo^T + bo + x -> LayerNorm -> ReLU. 16 rows/block, 64 blocks.
// ---------------------------------------------------------------------------
__global__ void __launch_bounds__(256) out_kernel(
        const float* __restrict__ x,  const float* __restrict__ Wo,
        const float* __restrict__ bo, const float* __restrict__ gamma,
        const float* __restrict__ beta, float* __restrict__ out) {
    __shared__ float Agc[16*68];
    __shared__ float WoS[128*64];
    int n0 = blockIdx.x * 16;
    int t  = threadIdx.x;
    int w = t >> 5, lane = t & 31;

    // fragments: n = (lane>>3)+4r (r 0..3), e = et*128 + 16w + 2*(lane&7)+c (c 0..1)
    int nlf = lane >> 3;
    int elf = 16*w + 2*(lane & 7);
    float acc[2][4][2];
    #pragma unroll
    for (int et = 0; et < 2; et++)
        #pragma unroll
        for (int r = 0; r < 4; r++)
            #pragma unroll
            for (int c = 0; c < 2; c++) acc[et][r][c] = 0.f;

    for (int dt = 0; dt < 4; dt++) {
        __syncthreads();
        {
            int ii = t >> 4, q = t & 15;
            *(float4*)&Agc[ii*68 + q*4] =
                *(const float4*)&g_agg[(n0+ii)*DD + dt*64 + q*4];
        }
        for (int et = 0; et < 2; et++) {
            if (et == 1) __syncthreads();
            #pragma unroll
            for (int r = 0; r < 8; r++) {
                int idx = t + 256*r;
                int row = idx >> 4, q = idx & 15;
                *(float4*)&WoS[row*64 + ((q ^ (row&15))<<2)] =
                    *(const float4*)&Wo[(et*128+row)*DD + dt*64 + q*4];
            }
            __syncthreads();
            #pragma unroll 8
            for (int q16 = 0; q16 < 16; q16++) {
                float4 a[4], bfr[2];
                #pragma unroll
                for (int r = 0; r < 4; r++)
                    a[r] = *(const float4*)&Agc[(nlf+4*r)*68 + q16*4];
                #pragma unroll
                for (int c = 0; c < 2; c++) {
                    int row = elf + c;
                    bfr[c] = *(const float4*)&WoS[row*64 + ((q16 ^ (row&15))<<2)];
                }
                #pragma unroll
                for (int r = 0; r < 4; r++)
                    #pragma unroll
                    for (int c = 0; c < 2; c++)
                        acc[et][r][c] += a[r].x*bfr[c].x + a[r].y*bfr[c].y
                                       + a[r].z*bfr[c].z + a[r].w*bfr[c].w;
            }
            __syncthreads();
        }
    }

    // epilogue: bias + residual into shared (reuse WoS as OutS[16*256])
    float* OutS = WoS;
    #pragma unroll
    for (int et = 0; et < 2; et++)
        #pragma unroll
        for (int r = 0; r < 4; r++) {
            int n = nlf + 4*r;
            #pragma unroll
            for (int c = 0; c < 2; c++) {
                int e = et*128 + elf + c;
                OutS[n*256 + e] = acc[et][r][c] + bo[e] + x[(n0+n)*DD + e];
            }
        }
    __syncthreads();

    // LayerNorm + ReLU, warp per 2 rows
    #pragma unroll
    for (int rr = 0; rr < 2; rr++) {
        int ii = w*2 + rr;
        float vals[8];
        float sum = 0.f, sq = 0.f;
        #pragma unroll
        for (int k = 0; k < 8; k++) {
            vals[k] = OutS[ii*256 + lane + 32*k];
            sum += vals[k]; sq += vals[k]*vals[k];
        }
        #pragma unroll
        for (int o = 16; o > 0; o >>= 1) {
            sum += __shfl_xor_sync(0xffffffff, sum, o);
            sq  += __shfl_xor_sync(0xffffffff, sq,  o);
        }
        float mu  = sum * (1.f/256.f);
        float var = sq  * (1.f/256.f) - mu*mu;
        float inv = rsqrtf(var + 1e-5f);
        #pragma unroll
        for (int k = 0; k < 8; k++) {
            int e = lane + 32*k;
            float y = (vals[k] - mu) * inv * gamma[e] + beta[e];
            out[(n0+ii)*DD + e] = fmaxf(y, 0.f);
        }
    }
}

extern "C" void kernel_launch(void* const* d_in, const int* in_sizes, int n_in,
                              void* d_out, int out_size) {
    const float* x       = (const float*)d_in[0];
    const int*   spatial = (const int*)  d_in[1];
    const float* Wq      = (const float*)d_in[2];
    const float* bq      = (const float*)d_in[3];
    const float* Wk      = (const float*)d_in[4];
    const float* bk      = (const float*)d_in[5];
    const float* Wv      = (const float*)d_in[6];
    const float* bv      = (const float*)d_in[7];
    const float* rel_k   = (const float*)d_in[8];
    const float* rel_v   = (const float*)d_in[9];
    const float* Wo      = (const float*)d_in[10];
    const float* bo      = (const float*)d_in[11];
    const float* gamma   = (const float*)d_in[12];
    const float* beta    = (const float*)d_in[13];
    float* out = (float*)d_out;

    // Non-stream runtime call: executes immediately even under capture;
    // idempotent & deterministic.
    cudaFuncSetAttribute(attn_kernel,
                         cudaFuncAttributeMaxDynamicSharedMemorySize,
                         ATTN_SMEM_FLOATS * (int)sizeof(float));

    qkv_kernel <<<dim3(16, 4, 3), 128>>>(x, Wq, Wk, Wv, bq, bk, bv);
    attn_kernel<<<dim3(16, 4, 4), 256, ATTN_SMEM_FLOATS * sizeof(float)>>>(
        spatial, rel_k, rel_v);
    out_kernel <<<64, 256>>>(x, Wo, bo, gamma, beta, out);
}

// round 7
// speedup vs baseline: 1.6764x; 1.1916x over previous
#include <cuda_runtime.h>

#define BB 4
#define TT 256
#define DD 256
#define HH 4
#define DKK 64
#define NREL 64
#define NT (BB*TT)   // 1024

__device__ float g_q[NT*DD];
__device__ float g_k[NT*DD];
__device__ float g_v[NT*DD];
__device__ float g_agg[NT*DD];

// ---------------------------------------------------------------------------
// K1: fused QKV projection. out[n,e] = sum_d x[n,d]*W[e,d] + b[e]
// 128 threads, tile 64n x 32e (grid 16x8x3 = 384 for load balance),
// K-chunks 64, swizzled smem, float4 everywhere. Fragment: 4n x 4e.
// ---------------------------------------------------------------------------
__global__ void __launch_bounds__(128) qkv_kernel(
        const float* __restrict__ x,
        const float* __restrict__ Wq, const float* __restrict__ Wk,
        const float* __restrict__ Wv,
        const float* __restrict__ bq, const float* __restrict__ bk,
        const float* __restrict__ bv) {
    __shared__ float As[64*64];
    __shared__ float Bs[32*64];
    int n0 = blockIdx.x * 64;
    int e0 = blockIdx.y * 32;
    const float* W; const float* bias; float* out;
    if (blockIdx.z == 0)      { W = Wq; bias = bq; out = g_q; }
    else if (blockIdx.z == 1) { W = Wk; bias = bk; out = g_k; }
    else                      { W = Wv; bias = bv; out = g_v; }

    int t  = threadIdx.x;
    int el = t & 7;          // e = e0 + el + 8j, j=0..3
    int nl = t >> 3;         // n = n0 + nl + 16i, i=0..3
    float acc[4][4];
    #pragma unroll
    for (int i = 0; i < 4; i++)
        #pragma unroll
        for (int j = 0; j < 4; j++) acc[i][j] = 0.f;

    int lrow = t >> 4;       // 0..7
    int lq   = t & 15;       // quad 0..15

    for (int d0 = 0; d0 < DD; d0 += 64) {
        __syncthreads();
        #pragma unroll
        for (int r = 0; r < 8; r++) {
            int row = lrow + 8*r;
            *(float4*)&As[row*64 + ((lq ^ (row&15))<<2)] =
                *(const float4*)&x[(n0+row)*DD + d0 + lq*4];
        }
        #pragma unroll
        for (int r = 0; r < 4; r++) {
            int row = lrow + 8*r;
            *(float4*)&Bs[row*64 + ((lq ^ (row&15))<<2)] =
                *(const float4*)&W[(e0+row)*DD + d0 + lq*4];
        }
        __syncthreads();
        #pragma unroll 16
        for (int q16 = 0; q16 < 16; q16++) {
            float4 a[4], b[4];
            #pragma unroll
            for (int i = 0; i < 4; i++) {
                int row = nl + 16*i;
                a[i] = *(const float4*)&As[row*64 + ((q16 ^ (row&15))<<2)];
            }
            #pragma unroll
            for (int j = 0; j < 4; j++) {
                int row = el + 8*j;
                b[j] = *(const float4*)&Bs[row*64 + ((q16 ^ (row&15))<<2)];
            }
            #pragma unroll
            for (int i = 0; i < 4; i++)
                #pragma unroll
                for (int j = 0; j < 4; j++) {
                    acc[i][j] += a[i].x*b[j].x + a[i].y*b[j].y
                               + a[i].z*b[j].z + a[i].w*b[j].w;
                }
        }
    }
    #pragma unroll
    for (int i = 0; i < 4; i++) {
        int n = n0 + nl + 16*i;
        #pragma unroll
        for (int j = 0; j < 4; j++) {
            int e = e0 + el + 8*j;
            out[n*DD + e] = acc[i][j] + bias[e];
        }
    }
}

// ---------------------------------------------------------------------------
// K2: fused attention. One block per (b, h, 16-row i-tile). 256 threads.
// Dynamic smem: full K/V tile resident (256x68).  (UNCHANGED from R6)
// ---------------------------------------------------------------------------
#define ATTN_SMEM_FLOATS (256*68 + 16*68 + 16*68 + 16*260 + 16*68)
// layout: KVs[256*68] | Qs[16*68] | QRs[16*68] | Ss[16*260] | Ws[16*68]

extern __shared__ float sm[];

__global__ void __launch_bounds__(256) attn_kernel(
        const int*  __restrict__ spatial,
        const float* __restrict__ rel_k,
        const float* __restrict__ rel_v) {
    float* KVs = sm;
    float* Qs  = KVs + 256*68;
    float* QRs = Qs  + 16*68;
    float* Ss  = QRs + 16*68;
    float* Ws  = Ss  + 16*260;

    int it = blockIdx.x, h = blockIdx.y, b = blockIdx.z;
    int i0 = it * 16;
    int t  = threadIdx.x;
    int hd = h * DKK;
    int w = t >> 5, lane = t & 31;

    // P0: Q tile [16x64] + rel_k [64x64] + zero Ws
    {
        int ii = t >> 4, q = t & 15;
        *(float4*)&Qs[ii*68 + q*4] =
            *(const float4*)&g_q[(b*TT + i0 + ii)*DD + hd + q*4];
        #pragma unroll
        for (int r = 0; r < 4; r++) {
            int row = (t>>4) + 16*r;
            *(float4*)&KVs[row*68 + q*4] =
                *(const float4*)&rel_k[row*DD + hd + q*4];
        }
    }
    for (int idx = t; idx < 16*68; idx += 256) Ws[idx] = 0.f;
    __syncthreads();

    // P2: qr[ii][rel] = <Q_ii, rel_k[rel]>
    #pragma unroll
    for (int rr = 0; rr < 4; rr++) {
        int o = t + 256*rr;
        int ii = o >> 6, rel = o & 63;
        float s = 0.f;
        #pragma unroll
        for (int q16 = 0; q16 < 16; q16++) {
            float4 qv = *(const float4*)&Qs[ii*68 + q16*4];
            float4 kv = *(const float4*)&KVs[rel*68 + q16*4];
            s += qv.x*kv.x + qv.y*kv.y + qv.z*kv.z + qv.w*kv.w;
        }
        QRs[ii*68 + rel] = s;
    }
    __syncthreads();

    // load full K [256x64]
    {
        int q = t & 15;
        #pragma unroll
        for (int r = 0; r < 16; r++) {
            int row = (t>>4) + 16*r;
            *(float4*)&KVs[row*68 + q*4] =
                *(const float4*)&g_k[(b*TT + row)*DD + hd + q*4];
        }
    }
    __syncthreads();

    // P3: scores. warp w owns j in [32w, 32w+32). thread: i = il+4r, j = 32w+jl+8c.
    {
        int jl = lane & 7, il = lane >> 3;
        float s[4][4];
        #pragma unroll
        for (int r = 0; r < 4; r++)
            #pragma unroll
            for (int c = 0; c < 4; c++) s[r][c] = 0.f;
        #pragma unroll 8
        for (int q16 = 0; q16 < 16; q16++) {
            float4 qv[4], kv[4];
            #pragma unroll
            for (int r = 0; r < 4; r++)
                qv[r] = *(const float4*)&Qs[(il+4*r)*68 + q16*4];
            #pragma unroll
            for (int c = 0; c < 4; c++)
                kv[c] = *(const float4*)&KVs[(32*w + jl + 8*c)*68 + q16*4];
            #pragma unroll
            for (int r = 0; r < 4; r++)
                #pragma unroll
                for (int c = 0; c < 4; c++)
                    s[r][c] += qv[r].x*kv[c].x + qv[r].y*kv[c].y
                             + qv[r].z*kv[c].z + qv[r].w*kv[c].w;
        }
        #pragma unroll
        for (int r = 0; r < 4; r++) {
            int i = il + 4*r;
            #pragma unroll
            for (int c = 0; c < 4; c++) {
                int j = 32*w + jl + 8*c;
                int rel = spatial[(b*TT + i0 + i)*TT + j];
                Ss[i*260 + j] = (s[r][c] + QRs[i*68 + rel]) * 0.125f;
            }
        }
    }
    __syncthreads();

    // load V over K (all warps past P3 due to sync above)
    {
        int q = t & 15;
        #pragma unroll
        for (int r = 0; r < 16; r++) {
            int row = (t>>4) + 16*r;
            *(float4*)&KVs[row*68 + q*4] =
                *(const float4*)&g_v[(b*TT + row)*DD + hd + q*4];
        }
    }

    // P4: softmax, warp w handles rows 2w, 2w+1
    #pragma unroll
    for (int rr = 0; rr < 2; rr++) {
        int ii = w*2 + rr;
        float vals[8];
        float vmax = -1e30f;
        #pragma unroll
        for (int k = 0; k < 8; k++) {
            vals[k] = Ss[ii*260 + lane + 32*k];
            vmax = fmaxf(vmax, vals[k]);
        }
        #pragma unroll
        for (int o = 16; o > 0; o >>= 1)
            vmax = fmaxf(vmax, __shfl_xor_sync(0xffffffff, vmax, o));
        float sum = 0.f;
        #pragma unroll
        for (int k = 0; k < 8; k++) { vals[k] = __expf(vals[k] - vmax); sum += vals[k]; }
        #pragma unroll
        for (int o = 16; o > 0; o >>= 1)
            sum += __shfl_xor_sync(0xffffffff, sum, o);
        float inv = 1.f / sum;
        #pragma unroll
        for (int k = 0; k < 8; k++)
            Ss[ii*260 + lane + 32*k] = vals[k] * inv;
    }
    __syncthreads();   // covers V load + softmax completion

    // P5: relation histogram (thread t owns column j=t)
    #pragma unroll 4
    for (int ii = 0; ii < 16; ii++) {
        int rel = spatial[(b*TT + i0 + ii)*TT + t];
        atomicAdd(&Ws[ii*68 + rel], Ss[ii*260 + t]);
    }

    // P6a: agg partial = attn @ V. warp: iy=w&3, jh=w>>2.
    int iy = w & 3, jh = w >> 2;
    int il2 = lane >> 4, dq = lane & 15;
    int ib = 4*iy + 2*il2;
    float a6[2][4];
    #pragma unroll
    for (int r = 0; r < 2; r++)
        #pragma unroll
        for (int c = 0; c < 4; c++) a6[r][c] = 0.f;
    {
        int jbeg = 128*jh, jend = jbeg + 128;
        #pragma unroll 4
        for (int jj = jbeg; jj < jend; jj += 2) {
            float2 p0 = *(const float2*)&Ss[ib*260 + jj];
            float2 p1 = *(const float2*)&Ss[(ib+1)*260 + jj];
            float4 v0 = *(const float4*)&KVs[jj*68 + 4*dq];
            float4 v1 = *(const float4*)&KVs[(jj+1)*68 + 4*dq];
            a6[0][0] += p0.x*v0.x + p0.y*v1.x;
            a6[0][1] += p0.x*v0.y + p0.y*v1.y;
            a6[0][2] += p0.x*v0.z + p0.y*v1.z;
            a6[0][3] += p0.x*v0.w + p0.y*v1.w;
            a6[1][0] += p1.x*v0.x + p1.y*v1.x;
            a6[1][1] += p1.x*v0.y + p1.y*v1.y;
            a6[1][2] += p1.x*v0.z + p1.y*v1.z;
            a6[1][3] += p1.x*v0.w + p1.y*v1.w;
        }
    }
    __syncthreads();   // Ws complete (P5), KVs free

    // load rel_v into KVs[0:64]
    {
        int q = t & 15;
        #pragma unroll
        for (int r = 0; r < 4; r++) {
            int row = (t>>4) + 16*r;
            *(float4*)&KVs[row*68 + q*4] =
                *(const float4*)&rel_v[row*DD + hd + q*4];
        }
    }
    __syncthreads();

    // P6b: += w @ rel_v
    {
        int rbeg = 32*jh, rend = rbeg + 32;
        #pragma unroll 4
        for (int rr = rbeg; rr < rend; rr += 2) {
            float2 p0 = *(const float2*)&Ws[ib*68 + rr];
            float2 p1 = *(const float2*)&Ws[(ib+1)*68 + rr];
            float4 v0 = *(const float4*)&KVs[rr*68 + 4*dq];
            float4 v1 = *(const float4*)&KVs[(rr+1)*68 + 4*dq];
            a6[0][0] += p0.x*v0.x + p0.y*v1.x;
            a6[0][1] += p0.x*v0.y + p0.y*v1.y;
            a6[0][2] += p0.x*v0.z + p0.y*v1.z;
            a6[0][3] += p0.x*v0.w + p0.y*v1.w;
            a6[1][0] += p1.x*v0.x + p1.y*v1.x;
            a6[1][1] += p1.x*v0.y + p1.y*v1.y;
            a6[1][2] += p1.x*v0.z + p1.y*v1.z;
            a6[1][3] += p1.x*v0.w + p1.y*v1.w;
        }
    }

    // reduce two j-halves via shared (reuse Qs as 16x64 buffer)
    float* Rs = Qs;
    if (jh == 0) {
        #pragma unroll
        for (int r = 0; r < 2; r++)
            *(float4*)&Rs[(ib+r)*64 + 4*dq] = *(float4*)&a6[r][0];
    }
    __syncthreads();
    if (jh == 1) {
        #pragma unroll
        for (int r = 0; r < 2; r++) {
            float4 o = *(const float4*)&Rs[(ib+r)*64 + 4*dq];
            o.x += a6[r][0]; o.y += a6[r][1]; o.z += a6[r][2]; o.w += a6[r][3];
            *(float4*)&g_agg[(b*TT + i0 + ib + r)*DD + hd + 4*dq] = o;
        }
    }
}

// ---------------------------------------------------------------------------
// K3: out = agg @ Wo^T + bo + x -> LayerNorm -> ReLU.
// 8 rows/block -> 128 blocks (single balanced wave on 148 SMs).
// ---------------------------------------------------------------------------
__global__ void __launch_bounds__(256) out_kernel(
        const float* __restrict__ x,  const float* __restrict__ Wo,
        const float* __restrict__ bo, const float* __restrict__ gamma,
        const float* __restrict__ beta, float* __restrict__ out) {
    __shared__ float Agc[8*68];
    __shared__ float WoS[128*64];
    int n0 = blockIdx.x * 8;
    int t  = threadIdx.x;
    int w = t >> 5, lane = t & 31;

    // fragments: n = (lane>>3) + 4r (r 0..1), e = et*128 + 16w + 2*(lane&7)+c
    int nlf = lane >> 3;             // 0..3
    int elf = 16*w + 2*(lane & 7);
    float acc[2][2][2];
    #pragma unroll
    for (int et = 0; et < 2; et++)
        #pragma unroll
        for (int r = 0; r < 2; r++)
            #pragma unroll
            for (int c = 0; c < 2; c++) acc[et][r][c] = 0.f;

    for (int dt = 0; dt < 4; dt++) {
        __syncthreads();
        if (t < 128) {
            int ii = t >> 4, q = t & 15;
            *(float4*)&Agc[ii*68 + q*4] =
                *(const float4*)&g_agg[(n0+ii)*DD + dt*64 + q*4];
        }
        for (int et = 0; et < 2; et++) {
            if (et == 1) __syncthreads();
            #pragma unroll
            for (int r = 0; r < 8; r++) {
                int idx = t + 256*r;
                int row = idx >> 4, q = idx & 15;
                *(float4*)&WoS[row*64 + ((q ^ (row&15))<<2)] =
                    *(const float4*)&Wo[(et*128+row)*DD + dt*64 + q*4];
            }
            __syncthreads();
            #pragma unroll 8
            for (int q16 = 0; q16 < 16; q16++) {
                float4 a[2], bfr[2];
                #pragma unroll
                for (int r = 0; r < 2; r++)
                    a[r] = *(const float4*)&Agc[(nlf+4*r)*68 + q16*4];
                #pragma unroll
                for (int c = 0; c < 2; c++) {
                    int row = elf + c;
                    bfr[c] = *(const float4*)&WoS[row*64 + ((q16 ^ (row&15))<<2)];
                }
                #pragma unroll
                for (int r = 0; r < 2; r++)
                    #pragma unroll
                    for (int c = 0; c < 2; c++)
                        acc[et][r][c] += a[r].x*bfr[c].x + a[r].y*bfr[c].y
                                       + a[r].z*bfr[c].z + a[r].w*bfr[c].w;
            }
            __syncthreads();
        }
    }

    // epilogue: bias + residual into shared (reuse WoS as OutS[8*256])
    float* OutS = WoS;
    #pragma unroll
    for (int et = 0; et < 2; et++)
        #pragma unroll
        for (int r = 0; r < 2; r++) {
            int n = nlf + 4*r;
            #pragma unroll
            for (int c = 0; c < 2; c++) {
                int e = et*128 + elf + c;
                OutS[n*256 + e] = acc[et][r][c] + bo[e] + x[(n0+n)*DD + e];
            }
        }
    __syncthreads();

    // LayerNorm + ReLU: warp w handles row w (8 warps, 8 rows)
    {
        int ii = w;
        float vals[8];
        float sum = 0.f, sq = 0.f;
        #pragma unroll
        for (int k = 0; k < 8; k++) {
            vals[k] = OutS[ii*256 + lane + 32*k];
            sum += vals[k]; sq += vals[k]*vals[k];
        }
        #pragma unroll
        for (int o = 16; o > 0; o >>= 1) {
            sum += __shfl_xor_sync(0xffffffff, sum, o);
            sq  += __shfl_xor_sync(0xffffffff, sq,  o);
        }
        float mu  = sum * (1.f/256.f);
        float var = sq  * (1.f/256.f) - mu*mu;
        float inv = rsqrtf(var + 1e-5f);
        #pragma unroll
        for (int k = 0; k < 8; k++) {
            int e = lane + 32*k;
            float y = (vals[k] - mu) * inv * gamma[e] + beta[e];
            out[(n0+ii)*DD + e] = fmaxf(y, 0.f);
        }
    }
}

extern "C" void kernel_launch(void* const* d_in, const int* in_sizes, int n_in,
                              void* d_out, int out_size) {
    const float* x       = (const float*)d_in[0];
    const int*   spatial = (const int*)  d_in[1];
    const float* Wq      = (const float*)d_in[2];
    const float* bq      = (const float*)d_in[3];
    const float* Wk      = (const float*)d_in[4];
    const float* bk      = (const float*)d_in[5];
    const float* Wv      = (const float*)d_in[6];
    const float* bv      = (const float*)d_in[7];
    const float* rel_k   = (const float*)d_in[8];
    const float* rel_v   = (const float*)d_in[9];
    const float* Wo      = (const float*)d_in[10];
    const float* bo      = (const float*)d_in[11];
    const float* gamma   = (const float*)d_in[12];
    const float* beta    = (const float*)d_in[13];
    float* out = (float*)d_out;

    // Non-stream runtime call: executes immediately even under capture;
    // idempotent & deterministic.
    cudaFuncSetAttribute(attn_kernel,
                         cudaFuncAttributeMaxDynamicSharedMemorySize,
                         ATTN_SMEM_FLOATS * (int)sizeof(float));

    qkv_kernel <<<dim3(16, 8, 3), 128>>>(x, Wq, Wk, Wv, bq, bk, bv);
    attn_kernel<<<dim3(16, 4, 4), 256, ATTN_SMEM_FLOATS * sizeof(float)>>>(
        spatial, rel_k, rel_v);
    out_kernel <<<128, 256>>>(x, Wo, bo, gamma, beta, out);
}